// round 6
// baseline (speedup 1.0000x reference)
#include <cuda_runtime.h>
#include <math.h>

#define NB 4
#define NV 4096
#define NT 8192
#define NP 4096
#define EPSF 1e-12f

#define TPB 128
#define PPT 4              // points per thread (2 packed f32x2 streams)
#define TILE 128           // triangles staged in smem per tile
#define CHUNKS 32
#define CHUNK_TRIS (NT / CHUNKS)
#define F4_PER_TRI 11      // 176 bytes per triangle, constants pre-duplicated

typedef unsigned long long ull;

static __device__ float g_pos[NB * NV * 3];
static __device__ float4 g_tri2[NB * NT * F4_PER_TRI];
static __device__ unsigned int g_dmin[NB * NP];
static __device__ float g_psum[32];
static __device__ float g_pcnt[32];

// ---------- packed f32x2 helpers (SASS FADD2/FMUL2/FFMA2) ----------
__device__ __forceinline__ ull f2x(float lo, float hi) {
    ull r; asm("mov.b64 %0, {%1, %2};" : "=l"(r) : "f"(lo), "f"(hi)); return r;
}
__device__ __forceinline__ ull f2x_add(ull a, ull b) {
    ull r; asm("add.rn.f32x2 %0, %1, %2;" : "=l"(r) : "l"(a), "l"(b)); return r;
}
__device__ __forceinline__ ull f2x_mul(ull a, ull b) {
    ull r; asm("mul.rn.f32x2 %0, %1, %2;" : "=l"(r) : "l"(a), "l"(b)); return r;
}
__device__ __forceinline__ ull f2x_fma(ull a, ull b, ull c) {
    ull r; asm("fma.rn.f32x2 %0, %1, %2, %3;" : "=l"(r) : "l"(a), "l"(b), "l"(c)); return r;
}
// zero-cost lane extraction (register-pair aliasing, no MOVs after copy-prop)
__device__ __forceinline__ float f2lo(ull v) { return __uint_as_float((unsigned)v); }
__device__ __forceinline__ float f2hi(ull v) { return __uint_as_float((unsigned)(v >> 32)); }

__device__ __forceinline__ float safe_inv(float x) {
    return (fabsf(x) < EPSF) ? 1.0f : (1.0f / x);
}

// Kernel 1: sigmoid + layout transpose (B,3,4096)->(B,4096,3).
__global__ void prep_kernel(const float* __restrict__ vertices) {
    int idx = blockIdx.x * blockDim.x + threadIdx.x;
    if (idx < NB * 3 * NV) {
        int b = idx / (3 * NV);
        int r = idx - b * 3 * NV;
        int d = r / NV;
        int w = r - d * NV;
        float v = vertices[idx];
        float s = 1.0f / (1.0f + expf(-v));
        g_pos[(b * NV + w) * 3 + d] = s;
    }
}

// Kernel 2: per-triangle orthonormal frame + 2D constants, duplicated pairs.
// 2D frame: A at origin, u along AB (B=(bx,0)), v in-plane (C=(cx,cy), cy>=0),
// n = u x v. 22 constants -> 11 f32x2 pairs:
//  p0:(ux,uy) p1:(uz,Ku) p2:(vx,vy) p3:(vz,Kv) p4:(nx,ny) p5:(nz,Kn)
//  p6:(nbx,cx) p7:(cy,ncx) p8:(ncy,dx) p9:(niac2,nac2) p10:(nibc2,nbc2)
__global__ void tri_kernel(const int* __restrict__ faces) {
    int idx = blockIdx.x * blockDim.x + threadIdx.x;
    if (idx >= NB * NT) return;
    int b = idx >> 13;
    int t = idx & (NT - 1);
    int i0 = faces[t * 3 + 0], i1 = faces[t * 3 + 1], i2 = faces[t * 3 + 2];
    const float* base = g_pos + b * NV * 3;
    float ax = base[i0 * 3 + 0], ay = base[i0 * 3 + 1], az = base[i0 * 3 + 2];
    float bxp = base[i1 * 3 + 0], byp = base[i1 * 3 + 1], bzp = base[i1 * 3 + 2];
    float cxp = base[i2 * 3 + 0], cyp = base[i2 * 3 + 1], czp = base[i2 * 3 + 2];
    float e1x = bxp - ax, e1y = byp - ay, e1z = bzp - az;
    float acx = cxp - ax, acy = cyp - ay, acz = czp - az;
    float l1 = e1x * e1x + e1y * e1y + e1z * e1z;
    float ux, uy, uz;
    if (l1 < EPSF) { ux = 1.0f; uy = 0.0f; uz = 0.0f; }
    else {
        float inv = 1.0f / sqrtf(l1);
        ux = e1x * inv; uy = e1y * inv; uz = e1z * inv;
    }
    // v = normalize(ac - (ac.u)u), with fallback when colinear/degenerate
    float du = acx * ux + acy * uy + acz * uz;
    float wx = acx - du * ux, wy = acy - du * uy, wz = acz - du * uz;
    float l2 = wx * wx + wy * wy + wz * wz;
    float vx, vy, vz;
    if (l2 < EPSF) {
        float tx = uy, ty = -ux, tz = 0.0f;           // cross(u, z-axis)
        float lt = tx * tx + ty * ty;
        if (lt < 1e-8f) { tx = -uz; ty = 0.0f; tz = ux; lt = tx * tx + tz * tz; }
        float inv = 1.0f / sqrtf(lt);
        vx = tx * inv; vy = ty * inv; vz = tz * inv;
    } else {
        float inv = 1.0f / sqrtf(l2);
        vx = wx * inv; vy = wy * inv; vz = wz * inv;
    }
    float nx = uy * vz - uz * vy;
    float ny = uz * vx - ux * vz;
    float nz = ux * vy - uy * vx;
    float Ku = -(ax * ux + ay * uy + az * uz);
    float Kv = -(ax * vx + ay * vy + az * vz);
    float Kn = -(ax * nx + ay * ny + az * nz);
    float bx = e1x * ux + e1y * uy + e1z * uz;        // B = (bx, 0)
    float cx = acx * ux + acy * uy + acz * uz;        // C = (cx, cy), cy >= 0
    float cy = acx * vx + acy * vy + acz * vz;
    float dx = cx - bx;
    float ac2 = cx * cx + cy * cy;
    float bc2 = dx * dx + cy * cy;
    float4* o = g_tri2 + (size_t)idx * F4_PER_TRI;
    o[0]  = make_float4(ux, ux, uy, uy);
    o[1]  = make_float4(uz, uz, Ku, Ku);
    o[2]  = make_float4(vx, vx, vy, vy);
    o[3]  = make_float4(vz, vz, Kv, Kv);
    o[4]  = make_float4(nx, nx, ny, ny);
    o[5]  = make_float4(nz, nz, Kn, Kn);
    o[6]  = make_float4(-bx, -bx, cx, cx);
    o[7]  = make_float4(cy, cy, -cx, -cx);
    o[8]  = make_float4(-cy, -cy, dx, dx);
    o[9]  = make_float4(-safe_inv(ac2), -safe_inv(ac2), -ac2, -ac2);
    o[10] = make_float4(-safe_inv(bc2), -safe_inv(bc2), -bc2, -bc2);
}

// Kernel 2b: init dmin (separate tiny launch so dist_kernel is launch #4 for ncu).
__global__ void initdmin_kernel() {
    int idx = blockIdx.x * blockDim.x + threadIdx.x;
    if (idx < NB * NP) g_dmin[idx] = 0x7F7FFFFFu;    // +FLT_MAX bits
}

// Min-of-features in the triangle's local frame, one triangle vs 2 packed points.
// x,y in-plane coords, z normal offset. Candidates:
//   vertices: pa2, pb2, pc2 (unconditional)
//   edge AB (on x-axis): y^2+z^2      if 0 < x < bx
//   edge AC:             pa2 - d2^2/ac2  if 0 < d2 < ac2
//   edge BC:             pb2 - e^2/bc2   if 0 < e < bc2
//   face:                z^2          if y>0 && (cy*x - cx*y)>0 && (dx*y - cy*xb)>0
__device__ __forceinline__ void tri_pair(const ulonglong2* __restrict__ tp,
                                         ull px, ull py, ull pz,
                                         float& m0, float& m1)
{
    ulonglong2 c0 = tp[0], c1 = tp[1], c2 = tp[2], c3 = tp[3], c4 = tp[4], c5 = tp[5];
    ull x = f2x_fma(c0.x, px, f2x_fma(c0.y, py, f2x_fma(c1.x, pz, c1.y)));
    ull y = f2x_fma(c2.x, px, f2x_fma(c2.y, py, f2x_fma(c3.x, pz, c3.y)));
    ull z = f2x_fma(c4.x, px, f2x_fma(c4.y, py, f2x_fma(c5.x, pz, c5.y)));
    ulonglong2 c6 = tp[6], c7 = tp[7], c8 = tp[8], c9 = tp[9], c10 = tp[10];
    ull z2  = f2x_mul(z, z);
    ull zy2 = f2x_fma(y, y, z2);
    ull pa2 = f2x_fma(x, x, zy2);
    ull xb  = f2x_add(x, c6.x);                       // x - bx
    ull pb2 = f2x_fma(xb, xb, zy2);
    ull xc  = f2x_add(x, c7.y);                       // x - cx
    ull yc  = f2x_add(y, c8.x);                       // y - cy
    ull pc2 = f2x_fma(xc, xc, f2x_fma(yc, yc, z2));
    ull d2  = f2x_fma(y, c7.x, f2x_mul(x, c6.y));     // x*cx + y*cy
    ull dAC = f2x_fma(f2x_mul(d2, d2), c9.x, pa2);
    ull gac = f2x_add(d2, c9.y);                      // d2 - ac2
    ull e   = f2x_fma(y, c7.x, f2x_mul(xb, c8.y));    // xb*dx + y*cy
    ull dBC = f2x_fma(f2x_mul(e, e), c10.x, pb2);
    ull gbc = f2x_add(e, c10.y);                      // e - bc2
    ull u0  = f2x_fma(x, c7.x, f2x_mul(y, c7.y));     // cy*x - cx*y
    ull w2  = f2x_fma(y, c8.y, f2x_mul(xb, c8.x));    // dx*y - cy*xb

    // lane 0
    {
        float m = fminf(fminf(f2lo(pa2), f2lo(pb2)), f2lo(pc2));
        if (f2lo(x) > 0.0f && f2lo(xb) < 0.0f) m = fminf(m, f2lo(zy2));
        if (f2lo(d2) > 0.0f && f2lo(gac) < 0.0f) m = fminf(m, f2lo(dAC));
        if (f2lo(e) > 0.0f && f2lo(gbc) < 0.0f) m = fminf(m, f2lo(dBC));
        if (f2lo(y) > 0.0f && f2lo(u0) > 0.0f && f2lo(w2) > 0.0f) m = fminf(m, f2lo(z2));
        m0 = fminf(m0, m);
    }
    // lane 1
    {
        float m = fminf(fminf(f2hi(pa2), f2hi(pb2)), f2hi(pc2));
        if (f2hi(x) > 0.0f && f2hi(xb) < 0.0f) m = fminf(m, f2hi(zy2));
        if (f2hi(d2) > 0.0f && f2hi(gac) < 0.0f) m = fminf(m, f2hi(dAC));
        if (f2hi(e) > 0.0f && f2hi(gbc) < 0.0f) m = fminf(m, f2hi(dBC));
        if (f2hi(y) > 0.0f && f2hi(u0) > 0.0f && f2hi(w2) > 0.0f) m = fminf(m, f2hi(z2));
        m1 = fminf(m1, m);
    }
}

// Kernel 3: brute-force min over triangles, packed f32x2, smem-staged tris.
__global__ void __launch_bounds__(TPB) dist_kernel(const float* __restrict__ pc) {
    __shared__ float4 sT[TILE * F4_PER_TRI];
    int b = blockIdx.z;
    int tid = threadIdx.x;
    const float* P = pc + (size_t)b * NP * 3;
    int ibase = blockIdx.y * (PPT * TPB) + tid;

    float px[PPT], py[PPT], pz[PPT];
#pragma unroll
    for (int k = 0; k < PPT; k++) {
        int i = ibase + k * TPB;
        px[k] = P[i * 3 + 0];
        py[k] = P[i * 3 + 1];
        pz[k] = P[i * 3 + 2];
    }
    ull px2[2], py2[2], pz2[2];
#pragma unroll
    for (int j = 0; j < 2; j++) {
        px2[j] = f2x(px[2 * j], px[2 * j + 1]);
        py2[j] = f2x(py[2 * j], py[2 * j + 1]);
        pz2[j] = f2x(pz[2 * j], pz[2 * j + 1]);
    }
    float dm[PPT];
#pragma unroll
    for (int k = 0; k < PPT; k++) dm[k] = 3.402823466e38f;

    const float4* triBase = g_tri2 + ((size_t)b * NT + (size_t)blockIdx.x * CHUNK_TRIS) * F4_PER_TRI;

    for (int tt = 0; tt < CHUNK_TRIS / TILE; tt++) {
        __syncthreads();
        const float4* src = triBase + (size_t)tt * TILE * F4_PER_TRI;
#pragma unroll
        for (int i = 0; i < F4_PER_TRI; i++)
            sT[tid + i * TPB] = src[tid + i * TPB];
        __syncthreads();
#pragma unroll 2
        for (int t = 0; t < TILE; t++) {
            const ulonglong2* tp = reinterpret_cast<const ulonglong2*>(sT + t * F4_PER_TRI);
            tri_pair(tp, px2[0], py2[0], pz2[0], dm[0], dm[1]);
            tri_pair(tp, px2[1], py2[1], pz2[1], dm[2], dm[3]);
        }
    }
#pragma unroll
    for (int k = 0; k < PPT; k++)
        atomicMin(&g_dmin[b * NP + ibase + k * TPB], __float_as_uint(dm[k]));
}

// Kernel 4a: parallel partial reduce. 32 blocks (8 slices x 4 batches) x 512 thr.
__global__ void reduceA_kernel(const float* __restrict__ pc) {
    __shared__ float sd[512];
    __shared__ float sc[512];
    int tid = threadIdx.x;
    int blk = blockIdx.x;
    int b = blk >> 3;
    int slice = blk & 7;
    int i = slice * 512 + tid;
    const float* p = pc + ((size_t)b * NP + i) * 3;
    float x = p[0], y = p[1], z = p[2];
    float m = (x != 0.0f || y != 0.0f || z != 0.0f) ? 1.0f : 0.0f;
    sd[tid] = __uint_as_float(g_dmin[b * NP + i]) * m;
    sc[tid] = m;
    __syncthreads();
    for (int s = 256; s > 0; s >>= 1) {
        if (tid < s) {
            sd[tid] += sd[tid + s];
            sc[tid] += sc[tid + s];
        }
        __syncthreads();
    }
    if (tid == 0) {
        g_psum[blk] = sd[0];
        g_pcnt[blk] = sc[0];
    }
}

// Kernel 4b: deterministic fixed-order final combine.
__global__ void reduceB_kernel(float* __restrict__ out) {
    if (threadIdx.x == 0) {
        float acc = 0.0f;
        for (int b = 0; b < NB; b++) {
            float s = 0.0f, c = 0.0f;
#pragma unroll
            for (int j = 0; j < 8; j++) {
                s += g_psum[b * 8 + j];
                c += g_pcnt[b * 8 + j];
            }
            acc += s / fmaxf(c, 1.0f);
        }
        out[0] = acc * (1.0f / NB);
    }
}

extern "C" void kernel_launch(void* const* d_in, const int* in_sizes, int n_in,
                              void* d_out, int out_size) {
    const float* vertices = (const float*)d_in[0];
    const float* pc = (const float*)d_in[1];
    const int* faces = (const int*)d_in[2];
    float* out = (float*)d_out;

    prep_kernel<<<(NB * 3 * NV + 255) / 256, 256>>>(vertices);          // launch 1
    tri_kernel<<<(NB * NT + 255) / 256, 256>>>(faces);                  // launch 2
    initdmin_kernel<<<(NB * NP + 255) / 256, 256>>>();                  // launch 3
    dist_kernel<<<dim3(CHUNKS, NP / (PPT * TPB), NB), TPB>>>(pc);       // launch 4 (ncu)
    reduceA_kernel<<<32, 512>>>(pc);                                    // launch 5
    reduceB_kernel<<<1, 32>>>(out);                                     // launch 6
}